// round 16
// baseline (speedup 1.0000x reference)
#include <cuda_runtime.h>
#include <cuda_fp16.h>
#include <math.h>
#include <stdint.h>

#define NB 32768
#define HD 512
#define DV 256
#define NP 512
#define RHO_MAXF 9.0f
#define DELTAF 0.001f
#define EPSF 1e-8f
#define PIF 3.14159265358979f

// ---------------- scratch (__device__ globals: no allocations allowed) ----------------
__device__ __half g_hEnt[NB*HD];
__device__ __half g_hRel[NB*HD];
__device__ __half g_hLab[NB*HD];
__device__ __half g_hH0[NB*HD];   // layer-1 hidden; reused as fp16 Vh after layer 2
__device__ __half g_hH1[NB*HD];   // layer-1 hidden; reused as fp16 Vt
__device__ __half g_hH2[NB*HD];   // layer-1 hidden; reused as fp16 TH
__device__ __half g_hEh[NB*HD];
__device__ __half g_hEr[NB*HD];
__device__ __half g_hEt[NB*HD];
__device__ __half g_hW1[HD*HD];
__device__ __half g_hW2[HD*HD];
__device__ __half g_hWv[DV*HD];
__device__ __half g_hWt[NP*HD];

__device__ __forceinline__ float softplusf(float x) {
    return (x > 20.f) ? x : log1pf(expf(x));
}

__device__ __forceinline__ float fast_tanh(float x) {
    float y;
    asm("tanh.approx.f32 %0, %1;" : "=f"(y) : "f"(x));
    return y;
}

// sin(pi*t), cos(pi*t) for t in [-1,1] on the FMA pipe (no MUFU sin/cos, no F2I).
__device__ __forceinline__ void sincospi_t(float t, float& s, float& c) {
    float at = fabsf(t);
    bool f1 = at > 0.5f;
    float b = f1 ? (1.0f - at) : at;
    bool f2 = b > 0.25f;
    float d = f2 ? (0.5f - b) : b;
    float r = d * PIF;
    float w = r * r;
    float ps = fmaf(w, -1.9515296e-4f, 8.3321609e-3f);
    ps = fmaf(w, ps, -1.6666655e-1f);
    float sinr = fmaf(r * w, ps, r);
    float pc = fmaf(w, 2.4433157e-5f, -1.3887316e-3f);
    pc = fmaf(w, pc, 4.1666642e-2f);
    float cosr = fmaf(w * w, pc, fmaf(-0.5f, w, 1.0f));
    float sb = f2 ? cosr : sinr;
    float cb = f2 ? sinr : cosr;
    float ca = f1 ? -cb : cb;
    s = copysignf(sb, t);
    c = ca;
}

#define CP_ASYNC16(dst, src) \
    asm volatile("cp.async.cg.shared.global [%0], [%1], 16;" :: "r"(dst), "l"(src))
#define CP_COMMIT() asm volatile("cp.async.commit_group;" ::: "memory")
#define CP_WAIT2()  asm volatile("cp.async.wait_group 2;" ::: "memory")
#define CP_WAIT1()  asm volatile("cp.async.wait_group 1;" ::: "memory")

#define LDSM4(r0, r1, r2, r3, addr) \
    asm volatile("ldmatrix.sync.aligned.m8n8.x4.shared.b16 {%0,%1,%2,%3}, [%4];" \
                 : "=r"(r0), "=r"(r1), "=r"(r2), "=r"(r3) : "r"(addr))

__device__ __forceinline__ uint32_t smem_u32(const void* p) {
    uint32_t a;
    asm("{ .reg .u64 t; cvta.to.shared.u64 t, %1; cvt.u32.u64 %0, t; }" : "=r"(a) : "l"(p));
    return a;
}

// ---------------- fp32 -> fp16 conversions -------------------------------------------
__global__ void cvt3_f2h(const float* __restrict__ s0, const float* __restrict__ s1,
                         const float* __restrict__ s2,
                         __half* __restrict__ d0, __half* __restrict__ d1,
                         __half* __restrict__ d2)
{
    const float* s = (blockIdx.y == 0) ? s0 : (blockIdx.y == 1) ? s1 : s2;
    __half* d = (blockIdx.y == 0) ? d0 : (blockIdx.y == 1) ? d1 : d2;
    const int i = (blockIdx.x * blockDim.x + threadIdx.x) * 8;
    float4 a = *(const float4*)&s[i];
    float4 b = *(const float4*)&s[i + 4];
    __half2 h0 = __floats2half2_rn(a.x, a.y);
    __half2 h1 = __floats2half2_rn(a.z, a.w);
    __half2 h2 = __floats2half2_rn(b.x, b.y);
    __half2 h3 = __floats2half2_rn(b.z, b.w);
    uint4 o;
    o.x = *(uint32_t*)&h0; o.y = *(uint32_t*)&h1;
    o.z = *(uint32_t*)&h2; o.w = *(uint32_t*)&h3;
    *(uint4*)&d[i] = o;
}

// all 4 weight tensors in one launch (y selects tensor; x guarded by per-tensor size)
__global__ void cvtW_f2h(const float* __restrict__ s0, const float* __restrict__ s1,
                         const float* __restrict__ s2, const float* __restrict__ s3,
                         __half* __restrict__ d0, __half* __restrict__ d1,
                         __half* __restrict__ d2, __half* __restrict__ d3)
{
    const int y = blockIdx.y;
    const float* s = (y == 0) ? s0 : (y == 1) ? s1 : (y == 2) ? s2 : s3;
    __half* d = (y == 0) ? d0 : (y == 1) ? d1 : (y == 2) ? d2 : d3;
    const int n = (y == 2) ? (DV * HD) : (HD * HD);
    const int i = (blockIdx.x * blockDim.x + threadIdx.x) * 8;
    if (i >= n) return;
    float4 a = *(const float4*)&s[i];
    float4 b = *(const float4*)&s[i + 4];
    __half2 h0 = __floats2half2_rn(a.x, a.y);
    __half2 h1 = __floats2half2_rn(a.z, a.w);
    __half2 h2 = __floats2half2_rn(b.x, b.y);
    __half2 h3 = __floats2half2_rn(b.z, b.w);
    uint4 o;
    o.x = *(uint32_t*)&h0; o.y = *(uint32_t*)&h1;
    o.z = *(uint32_t*)&h2; o.w = *(uint32_t*)&h3;
    *(uint4*)&d[i] = o;
}

// ---------------- FP16 tensor-core NT GEMM (128x64 block, 3 CTA/SM) ------------------
// C[M,N] = A[M,512] * W[N,512]^T + bias, fp32 accumulate.
// Block 128M x 64N, 8 warps (4m x 2n), warp tile 32x32, KTILE=32 (2 k16 steps),
// 3-stage cp.async, ldmatrix.x4 fragments. Smem stride 20 words.
// mode bits: 1=relu, 16=+residual fp16(R), 8=store fp16 Ch
#define SMS 20
#define KDIM 512
#define KT 32
#define NKT (KDIM / KT)            // 16
#define SA_WORDS (128 * SMS)       // 2560
#define SB_WORDS (64 * SMS)        // 1280
#define STG_WORDS (SA_WORDS + SB_WORDS)  // 3840
#define STG_BYTES (STG_WORDS * 4)        // 15360
#define GEMM_SMEM_BYTES (3 * STG_BYTES)  // 46080

__global__ __launch_bounds__(256, 3)
void gemm_h(const __half* __restrict__ A0, const __half* __restrict__ A1,
            const __half* __restrict__ A2,
            const __half* __restrict__ W, const float* __restrict__ bias,
            const __half* __restrict__ R0, const __half* __restrict__ R1,
            const __half* __restrict__ R2,
            __half* __restrict__ Ch0, __half* __restrict__ Ch1, __half* __restrict__ Ch2,
            int N, int mode)
{
    extern __shared__ __align__(16) uint32_t smem[];
    const int tid = threadIdx.x, wid = tid >> 5, lane = tid & 31;
    const int g = lane >> 2, tg = lane & 3;
    const int z = blockIdx.z;
    const __half* A = (z == 0) ? A0 : (z == 1) ? A1 : A2;
    const __half* R = (z == 0) ? R0 : (z == 1) ? R1 : R2;
    __half*      Ch = (z == 0) ? Ch0 : (z == 1) ? Ch1 : Ch2;
    const int m0 = blockIdx.y * 128;
    const int n0 = blockIdx.x * 64;
    const int moff = (wid & 3) * 32;
    const int noff = (wid >> 2) * 32;
    const __half* Ag = A + (size_t)m0 * KDIM;
    const __half* Bg = W + (size_t)n0 * KDIM;

    const uint32_t sbase = smem_u32(smem);

    // ldmatrix per-lane addressing: row-in-group + k-half select
    const int lrow8 = ((lane >> 3) & 1) * 8 + (lane & 7);
    const int lk4   = (lane >> 4) * 4;
    uint32_t aoff[2], boff[2];
    #pragma unroll
    for (int mt = 0; mt < 2; mt++)
        aoff[mt] = ((moff + mt * 16 + lrow8) * SMS + lk4) * 4;
    #pragma unroll
    for (int ntp = 0; ntp < 2; ntp++)
        boff[ntp] = ((noff + ntp * 16 + lrow8) * SMS + lk4) * 4;

    float acc[2][4][4];
    #pragma unroll
    for (int mt = 0; mt < 2; mt++)
        #pragma unroll
        for (int nt = 0; nt < 4; nt++)
            #pragma unroll
            for (int q = 0; q < 4; q++) acc[mt][nt][q] = 0.f;

    // fill: A 512 16B-chunks (2/thread), B 256 chunks (1/thread)
    #define FILL_STAGE(stg, k0)                                                      \
    do {                                                                             \
        const uint32_t wA = sbase + (stg) * STG_BYTES;                               \
        const uint32_t wB = wA + SA_WORDS * 4;                                       \
        _Pragma("unroll")                                                            \
        for (int p = 0; p < 2; p++) {                                                \
            const int c = tid + 256 * p;                                             \
            const int row = c >> 2;                                                  \
            CP_ASYNC16(wA + (row * SMS + (c & 3) * 4) * 4,                           \
                       &Ag[(size_t)row * KDIM + (k0) + (c & 3) * 8]);                \
        }                                                                            \
        {                                                                            \
            const int row = tid >> 2;                                                \
            CP_ASYNC16(wB + (row * SMS + (tid & 3) * 4) * 4,                         \
                       &Bg[(size_t)row * KDIM + (k0) + (tid & 3) * 8]);              \
        }                                                                            \
    } while (0)

    FILL_STAGE(0, 0);  CP_COMMIT();
    FILL_STAGE(1, KT); CP_COMMIT();
    CP_WAIT1();
    __syncthreads();

    for (int t = 0; t < NKT; t++) {
        if (t + 2 < NKT) { FILL_STAGE((t + 2) % 3, (t + 2) * KT); }
        CP_COMMIT();
        CP_WAIT2();
        __syncthreads();

        const uint32_t Ab = sbase + (t % 3) * STG_BYTES;
        const uint32_t Bb = Ab + SA_WORDS * 4;

        #pragma unroll
        for (int ks = 0; ks < 2; ks++) {
            const uint32_t kb4 = ks * 32;
            uint32_t af[2][4], bf[4][2];
            #pragma unroll
            for (int mt = 0; mt < 2; mt++)
                LDSM4(af[mt][0], af[mt][1], af[mt][2], af[mt][3], Ab + aoff[mt] + kb4);
            #pragma unroll
            for (int ntp = 0; ntp < 2; ntp++)
                LDSM4(bf[2*ntp][0], bf[2*ntp+1][0], bf[2*ntp][1], bf[2*ntp+1][1],
                      Bb + boff[ntp] + kb4);
            #pragma unroll
            for (int mt = 0; mt < 2; mt++)
                #pragma unroll
                for (int nt = 0; nt < 4; nt++) {
                    asm volatile(
                        "mma.sync.aligned.m16n8k16.row.col.f32.f16.f16.f32 "
                        "{%0,%1,%2,%3}, {%4,%5,%6,%7}, {%8,%9}, {%0,%1,%2,%3};"
                        : "+f"(acc[mt][nt][0]), "+f"(acc[mt][nt][1]),
                          "+f"(acc[mt][nt][2]), "+f"(acc[mt][nt][3])
                        : "r"(af[mt][0]), "r"(af[mt][1]), "r"(af[mt][2]), "r"(af[mt][3]),
                          "r"(bf[nt][0]), "r"(bf[nt][1]));
                }
        }
        __syncthreads();
    }

    // ---- epilogue ----
    #pragma unroll
    for (int mt = 0; mt < 2; mt++) {
        #pragma unroll
        for (int nt = 0; nt < 4; nt++) {
            const int n = n0 + noff + nt * 8 + 2 * tg;
            const int ra = m0 + moff + mt * 16 + g;
            const int rb = ra + 8;
            float bx = bias[n], by = bias[n + 1];
            float2 v0 = make_float2(acc[mt][nt][0] + bx, acc[mt][nt][1] + by);
            float2 v1 = make_float2(acc[mt][nt][2] + bx, acc[mt][nt][3] + by);
            if (mode & 1) {
                v0.x = fmaxf(v0.x, 0.f); v0.y = fmaxf(v0.y, 0.f);
                v1.x = fmaxf(v1.x, 0.f); v1.y = fmaxf(v1.y, 0.f);
            }
            if (mode & 16) {
                float2 r0v = __half22float2(*(const __half2*)&R[(size_t)ra * N + n]);
                float2 r1v = __half22float2(*(const __half2*)&R[(size_t)rb * N + n]);
                v0.x += r0v.x; v0.y += r0v.y;
                v1.x += r1v.x; v1.y += r1v.y;
            }
            if (mode & 8) {
                __half2 h0 = __floats2half2_rn(v0.x, v0.y);
                __half2 h1 = __floats2half2_rn(v1.x, v1.y);
                *(__half2*)&Ch[(size_t)ra * N + n] = h0;
                *(__half2*)&Ch[(size_t)rb * N + n] = h1;
            }
        }
    }
}

// ================== warp-per-row fused gemv + polar + rotation-scan + score ==========
#define FULLM 0xffffffffu

__device__ __forceinline__ void rot_pass(float* xl, const float* sl, const float* cl,
                                         int lane)
{
    float x0 = __shfl_sync(FULLM, xl[0], 0);
    float x1 = __shfl_sync(FULLM, xl[1], 0);
    float s0 = __shfl_sync(FULLM, sl[0], 0);
    float c0 = __shfl_sync(FULLM, cl[0], 0);
    float x0pre = c0 * x0 - s0 * x1;

    float nx[8];
    #pragma unroll
    for (int k = 0; k < 7; k++) nx[k] = xl[k + 1];
    nx[7] = __shfl_down_sync(FULLM, xl[0], 1);
    if (lane == 31) nx[7] = x0pre;

    float A = 1.f, B = 0.f;
    #pragma unroll
    for (int k = 0; k < 8; k++) {
        B = fmaf(sl[k], B, cl[k] * nx[k]);
        A *= sl[k];
    }
    #pragma unroll
    for (int d = 1; d < 32; d <<= 1) {
        float pA = __shfl_up_sync(FULLM, A, d);
        float pB = __shfl_up_sync(FULLM, B, d);
        if (lane >= d) {
            B = fmaf(A, pB, B);
            A *= pA;
        }
    }
    float eA = __shfl_up_sync(FULLM, A, 1);
    float eB = __shfl_up_sync(FULLM, B, 1);
    if (lane == 0) { eA = 1.f; eB = 0.f; }
    float cur = fmaf(eA, x0, eB);

    float w[8];
    #pragma unroll
    for (int k = 0; k < 8; k++) {
        w[k] = cl[k] * cur - sl[k] * nx[k];
        cur = fmaf(sl[k], cur, cl[k] * nx[k]);
    }
    float x0fin = __shfl_sync(FULLM, cur, 31);
    #pragma unroll
    for (int k = 0; k < 8; k++) xl[k] = w[k];
    if (lane == 0) xl[0] = x0fin;
}

__device__ __forceinline__ void load8h(const __half* p, float* v) {
    uint4 a = *(const uint4*)p;
    const __half2* hp = (const __half2*)&a;
    float2 f0 = __half22float2(hp[0]);
    float2 f1 = __half22float2(hp[1]);
    float2 f2 = __half22float2(hp[2]);
    float2 f3 = __half22float2(hp[3]);
    v[0]=f0.x; v[1]=f0.y; v[2]=f1.x; v[3]=f1.y;
    v[4]=f2.x; v[5]=f2.y; v[6]=f3.x; v[7]=f3.y;
}

__global__ __launch_bounds__(256)
void polar_score(const __half* __restrict__ Vh, const __half* __restrict__ Vt,
                 const __half* __restrict__ TH,
                 const __half* __restrict__ Eh, const __half* __restrict__ Er,
                 const __half* __restrict__ Et,
                 const float* __restrict__ Wre, const float* __restrict__ bre,
                 const float* __restrict__ Wrr, const float* __restrict__ brr,
                 const float* __restrict__ sim,
                 const float* __restrict__ ga_rho, const float* __restrict__ gb_rho,
                 const float* __restrict__ ga_phi, const float* __restrict__ gb_phi,
                 float* __restrict__ out)
{
    const int b = (blockIdx.x * blockDim.x + threadIdx.x) >> 5;
    const int lane = threadIdx.x & 31;
    if (b >= NB) return;

    // ---- fused gemv: s1 = Eh.Wre, s2 = Er.Wrr, s3 = Et.Wre (16 elems/lane) ----
    float s1 = 0.f, s2 = 0.f, s3 = 0.f;
    {
        const int k0 = lane * 16;
        float e[8], wv[8];
        #pragma unroll
        for (int hseg = 0; hseg < 2; hseg++) {
            const int k = k0 + hseg * 8;
            #pragma unroll
            for (int j = 0; j < 8; j += 4)
                *(float4*)&wv[j] = *(const float4*)&Wre[k + j];
            load8h(Eh + (size_t)b * HD + k, e);
            #pragma unroll
            for (int j = 0; j < 8; j++) s1 = fmaf(e[j], wv[j], s1);
            load8h(Et + (size_t)b * HD + k, e);
            #pragma unroll
            for (int j = 0; j < 8; j++) s3 = fmaf(e[j], wv[j], s3);
            #pragma unroll
            for (int j = 0; j < 8; j += 4)
                *(float4*)&wv[j] = *(const float4*)&Wrr[k + j];
            load8h(Er + (size_t)b * HD + k, e);
            #pragma unroll
            for (int j = 0; j < 8; j++) s2 = fmaf(e[j], wv[j], s2);
        }
    }

    // ---- load u_h, u_t + norms ----
    float uh[8], ut[8];
    load8h(Vh + (size_t)b * DV + lane * 8, uh);
    load8h(Vt + (size_t)b * DV + lane * 8, ut);

    float nh = 0.f, nt2 = 0.f;
    #pragma unroll
    for (int k = 0; k < 8; k++) { nh = fmaf(uh[k], uh[k], nh); nt2 = fmaf(ut[k], ut[k], nt2); }
    #pragma unroll
    for (int o = 16; o > 0; o >>= 1) {
        nh  += __shfl_xor_sync(FULLM, nh,  o);
        nt2 += __shfl_xor_sync(FULLM, nt2, o);
    }
    float ih = 1.f / (sqrtf(nh) + EPSF);
    float it = 1.f / (sqrtf(nt2) + EPSF);
    #pragma unroll
    for (int k = 0; k < 8; k++) { uh[k] *= ih; ut[k] *= it; }

    // ---- rotations ----
    float sl[8], cl[8], tv[8];
    load8h(TH + (size_t)b * NP + lane * 8, tv);
    #pragma unroll
    for (int k = 0; k < 8; k++)
        sincospi_t(fast_tanh(tv[k]), sl[k], cl[k]);

    float w[8];
    #pragma unroll
    for (int k = 0; k < 8; k++) w[k] = uh[k];
    rot_pass(w, sl, cl, lane);

    load8h(TH + (size_t)b * NP + 256 + lane * 8, tv);
    #pragma unroll
    for (int k = 0; k < 8; k++)
        sincospi_t(fast_tanh(tv[k]), sl[k], cl[k]);
    rot_pass(w, sl, cl, lane);

    // ---- dots + combined reduction (incl. gemv partials) ----
    float ssq = 0.f, dhr = 0.f, drt = 0.f, dht = 0.f;
    #pragma unroll
    for (int k = 0; k < 8; k++) {
        ssq = fmaf(w[k], w[k], ssq);
        dhr = fmaf(w[k], uh[k], dhr);
        drt = fmaf(w[k], ut[k], drt);
        dht = fmaf(uh[k], ut[k], dht);
    }
    #pragma unroll
    for (int o = 16; o > 0; o >>= 1) {
        ssq += __shfl_xor_sync(FULLM, ssq, o);
        dhr += __shfl_xor_sync(FULLM, dhr, o);
        drt += __shfl_xor_sync(FULLM, drt, o);
        dht += __shfl_xor_sync(FULLM, dht, o);
        s1  += __shfl_xor_sync(FULLM, s1,  o);
        s2  += __shfl_xor_sync(FULLM, s2,  o);
        s3  += __shfl_xor_sync(FULLM, s3,  o);
    }

    if (lane != 0) return;

    float nr = sqrtf(ssq);
    float inv_rot = 1.f / (nr + EPSF);
    float dhr_n = dhr * inv_rot;
    float dotc = fminf(fmaxf(dhr_n, -1.f + EPSF), 1.f - EPSF);
    float omega = acosf(dotc);
    float sin_om = sinf(omega);
    float sv = sim[b];
    float grho = 1.f / (1.f + expf(-(ga_rho[0] * sv + gb_rho[0])));
    float gphi = 1.f / (1.f + expf(-(ga_phi[0] * sv + gb_phi[0])));
    float ca, cb;
    if (omega > DELTAF) {
        float iso = 1.f / (sin_om + EPSF);
        ca = sinf((1.f - gphi) * omega) * iso;
        cb = sinf(gphi * omega) * iso;
    } else {
        ca = 1.f - gphi; cb = gphi;
    }
    float nrn = nr * inv_rot;
    float np2 = ca * ca + cb * cb * nrn * nrn + 2.f * ca * cb * dhr_n;
    float npv = sqrtf(fmaxf(np2, 0.f));
    float inv_np = 1.f / (npv + EPSF);
    float dpt = (ca * dht + cb * drt * inv_rot) * inv_np;

    float reh_v = s1 + bre[0];
    float rrr_v = s2 + brr[0];
    float ret_v = s3 + bre[0];
    float rho_h = fminf(softplusf(reh_v), RHO_MAXF);
    float rho_p = fminf(fmaxf(rho_h + rrr_v * grho, 0.f), RHO_MAXF);
    float rho_t = fminf(softplusf(ret_v), RHO_MAXF);
    out[b] = -coshf(rho_p) * coshf(rho_t) + sinhf(rho_p) * sinhf(rho_t) * dpt;
}

// ---------------- launch --------------------------------------------------------------
extern "C" void kernel_launch(void* const* d_in, const int* in_sizes, int n_in,
                              void* d_out, int out_size)
{
    const float* ent  = (const float*)d_in[0];
    const float* rel  = (const float*)d_in[1];
    const float* lab  = (const float*)d_in[2];
    const float* sim  = (const float*)d_in[3];
    const float* Wv   = (const float*)d_in[4];
    const float* bv   = (const float*)d_in[5];
    const float* Wre  = (const float*)d_in[6];
    const float* bre  = (const float*)d_in[7];
    const float* Wrr  = (const float*)d_in[8];
    const float* brr  = (const float*)d_in[9];
    const float* Wt   = (const float*)d_in[10];
    const float* bt   = (const float*)d_in[11];
    const float* ga_rho = (const float*)d_in[12];
    const float* gb_rho = (const float*)d_in[13];
    const float* ga_phi = (const float*)d_in[14];
    const float* gb_phi = (const float*)d_in[15];
    const float* W1   = (const float*)d_in[16];
    const float* b1   = (const float*)d_in[17];
    const float* W2   = (const float*)d_in[18];
    const float* b2   = (const float*)d_in[19];
    float* out = (float*)d_out;

    __half *hEnt, *hRel, *hLab, *hH0, *hH1, *hH2, *hEh, *hEr, *hEt;
    __half *hW1, *hW2, *hWv, *hWt;
    cudaGetSymbolAddress((void**)&hEnt, g_hEnt);
    cudaGetSymbolAddress((void**)&hRel, g_hRel);
    cudaGetSymbolAddress((void**)&hLab, g_hLab);
    cudaGetSymbolAddress((void**)&hH0,  g_hH0);
    cudaGetSymbolAddress((void**)&hH1,  g_hH1);
    cudaGetSymbolAddress((void**)&hH2,  g_hH2);
    cudaGetSymbolAddress((void**)&hEh,  g_hEh);
    cudaGetSymbolAddress((void**)&hEr,  g_hEr);
    cudaGetSymbolAddress((void**)&hEt,  g_hEt);
    cudaGetSymbolAddress((void**)&hW1,  g_hW1);
    cudaGetSymbolAddress((void**)&hW2,  g_hW2);
    cudaGetSymbolAddress((void**)&hWv,  g_hWv);
    cudaGetSymbolAddress((void**)&hWt,  g_hWt);

    cudaFuncSetAttribute(gemm_h, cudaFuncAttributeMaxDynamicSharedMemorySize,
                         GEMM_SMEM_BYTES);

    const int BIG = NB * HD;
    cvt3_f2h<<<dim3(BIG / (256 * 8), 3), 256>>>(ent, rel, lab, hEnt, hRel, hLab);
    cvtW_f2h<<<dim3((HD * HD) / (256 * 8), 4), 256>>>(W1, W2, Wv, Wt,
                                                      hW1, hW2, hWv, hWt);

    const dim3 blk(256);
    // layer 1: hH_z = fp16(relu(X_z @ W1^T + b1))             mode 1|8 = 9
    gemm_h<<<dim3(HD/64, NB/128, 3), blk, GEMM_SMEM_BYTES>>>(
        hEnt, hRel, hLab, hW1, b1, nullptr, nullptr, nullptr,
        hH0, hH1, hH2, HD, 9);
    // layer 2: hE_z = fp16(H_z @ W2^T + b2 + X_z[fp16])       mode 16|8 = 24
    gemm_h<<<dim3(HD/64, NB/128, 3), blk, GEMM_SMEM_BYTES>>>(
        hH0, hH1, hH2, hW2, b2, hEnt, hRel, hLab,
        hEh, hEr, hEt, HD, 24);
    // Wv projections -> fp16 (reuse hH0/hH1)                  mode 8
    gemm_h<<<dim3(DV/64, NB/128, 2), blk, GEMM_SMEM_BYTES>>>(
        hEh, hEt, nullptr, hWv, bv, nullptr, nullptr, nullptr,
        hH0, hH1, nullptr, DV, 8);
    // theta logits -> fp16 (reuse hH2)                        mode 8
    gemm_h<<<dim3(NP/64, NB/128, 1), blk, GEMM_SMEM_BYTES>>>(
        hEr, nullptr, nullptr, hWt, bt, nullptr, nullptr, nullptr,
        hH2, nullptr, nullptr, NP, 8);

    // fused warp-per-row: gemv (rho logits) + normalize + Givens scan + score
    polar_score<<<(NB * 32) / 256, 256>>>(hH0, hH1, hH2, hEh, hEr, hEt,
                                          Wre, bre, Wrr, brr, sim,
                                          ga_rho, gb_rho, ga_phi, gb_phi, out);
    (void)in_sizes; (void)n_in; (void)out_size;
}

// round 17
// speedup vs baseline: 1.1315x; 1.1315x over previous
#include <cuda_runtime.h>
#include <cuda_fp16.h>
#include <math.h>
#include <stdint.h>

#define NB 32768
#define HD 512
#define DV 256
#define NP 512
#define RHO_MAXF 9.0f
#define DELTAF 0.001f
#define EPSF 1e-8f
#define PIF 3.14159265358979f

// ---------------- scratch (__device__ globals: no allocations allowed) ----------------
__device__ __half g_hEnt[NB*HD];
__device__ __half g_hRel[NB*HD];
__device__ __half g_hLab[NB*HD];
__device__ __half g_hH0[NB*HD];   // layer-1 hidden; reused as fp16 Vh after layer 2
__device__ __half g_hH1[NB*HD];   // layer-1 hidden; reused as fp16 Vt
__device__ __half g_hH2[NB*HD];   // layer-1 hidden; reused as fp16 TH
__device__ __half g_hEh[NB*HD];
__device__ __half g_hEr[NB*HD];
__device__ __half g_hEt[NB*HD];
__device__ __half g_hW1[HD*HD];
__device__ __half g_hW2[HD*HD];
__device__ __half g_hWv[DV*HD];
__device__ __half g_hWt[NP*HD];

__device__ __forceinline__ float softplusf(float x) {
    return (x > 20.f) ? x : log1pf(expf(x));
}

__device__ __forceinline__ float fast_tanh(float x) {
    float y;
    asm("tanh.approx.f32 %0, %1;" : "=f"(y) : "f"(x));
    return y;
}

// sin(pi*t), cos(pi*t) for t in [-1,1] on the FMA pipe (no MUFU sin/cos, no F2I).
__device__ __forceinline__ void sincospi_t(float t, float& s, float& c) {
    float at = fabsf(t);
    bool f1 = at > 0.5f;
    float b = f1 ? (1.0f - at) : at;
    bool f2 = b > 0.25f;
    float d = f2 ? (0.5f - b) : b;
    float r = d * PIF;
    float w = r * r;
    float ps = fmaf(w, -1.9515296e-4f, 8.3321609e-3f);
    ps = fmaf(w, ps, -1.6666655e-1f);
    float sinr = fmaf(r * w, ps, r);
    float pc = fmaf(w, 2.4433157e-5f, -1.3887316e-3f);
    pc = fmaf(w, pc, 4.1666642e-2f);
    float cosr = fmaf(w * w, pc, fmaf(-0.5f, w, 1.0f));
    float sb = f2 ? cosr : sinr;
    float cb = f2 ? sinr : cosr;
    float ca = f1 ? -cb : cb;
    s = copysignf(sb, t);
    c = ca;
}

#define CP_ASYNC16(dst, src) \
    asm volatile("cp.async.cg.shared.global [%0], [%1], 16;" :: "r"(dst), "l"(src))
#define CP_COMMIT() asm volatile("cp.async.commit_group;" ::: "memory")
#define CP_WAIT1()  asm volatile("cp.async.wait_group 1;" ::: "memory")

#define LDSM4(r0, r1, r2, r3, addr) \
    asm volatile("ldmatrix.sync.aligned.m8n8.x4.shared.b16 {%0,%1,%2,%3}, [%4];" \
                 : "=r"(r0), "=r"(r1), "=r"(r2), "=r"(r3) : "r"(addr))

__device__ __forceinline__ uint32_t smem_u32(const void* p) {
    uint32_t a;
    asm("{ .reg .u64 t; cvta.to.shared.u64 t, %1; cvt.u32.u64 %0, t; }" : "=r"(a) : "l"(p));
    return a;
}

// ---------------- fp32 -> fp16 conversions -------------------------------------------
__global__ void cvt3_f2h(const float* __restrict__ s0, const float* __restrict__ s1,
                         const float* __restrict__ s2,
                         __half* __restrict__ d0, __half* __restrict__ d1,
                         __half* __restrict__ d2)
{
    const float* s = (blockIdx.y == 0) ? s0 : (blockIdx.y == 1) ? s1 : s2;
    __half* d = (blockIdx.y == 0) ? d0 : (blockIdx.y == 1) ? d1 : d2;
    const int i = (blockIdx.x * blockDim.x + threadIdx.x) * 8;
    float4 a = *(const float4*)&s[i];
    float4 b = *(const float4*)&s[i + 4];
    __half2 h0 = __floats2half2_rn(a.x, a.y);
    __half2 h1 = __floats2half2_rn(a.z, a.w);
    __half2 h2 = __floats2half2_rn(b.x, b.y);
    __half2 h3 = __floats2half2_rn(b.z, b.w);
    uint4 o;
    o.x = *(uint32_t*)&h0; o.y = *(uint32_t*)&h1;
    o.z = *(uint32_t*)&h2; o.w = *(uint32_t*)&h3;
    *(uint4*)&d[i] = o;
}

// all 4 weight tensors in one launch (y selects tensor; x guarded by per-tensor size)
__global__ void cvtW_f2h(const float* __restrict__ s0, const float* __restrict__ s1,
                         const float* __restrict__ s2, const float* __restrict__ s3,
                         __half* __restrict__ d0, __half* __restrict__ d1,
                         __half* __restrict__ d2, __half* __restrict__ d3)
{
    const int y = blockIdx.y;
    const float* s = (y == 0) ? s0 : (y == 1) ? s1 : (y == 2) ? s2 : s3;
    __half* d = (y == 0) ? d0 : (y == 1) ? d1 : (y == 2) ? d2 : d3;
    const int n = (y == 2) ? (DV * HD) : (HD * HD);
    const int i = (blockIdx.x * blockDim.x + threadIdx.x) * 8;
    if (i >= n) return;
    float4 a = *(const float4*)&s[i];
    float4 b = *(const float4*)&s[i + 4];
    __half2 h0 = __floats2half2_rn(a.x, a.y);
    __half2 h1 = __floats2half2_rn(a.z, a.w);
    __half2 h2 = __floats2half2_rn(b.x, b.y);
    __half2 h3 = __floats2half2_rn(b.z, b.w);
    uint4 o;
    o.x = *(uint32_t*)&h0; o.y = *(uint32_t*)&h1;
    o.z = *(uint32_t*)&h2; o.w = *(uint32_t*)&h3;
    *(uint4*)&d[i] = o;
}

// ---------------- FP16 tensor-core NT GEMM (128x128 block, KT=64, 2-stage) -----------
// C[M,N] = A[M,512] * W[N,512]^T + bias, fp32 accumulate.
// Block 128M x 128N, 8 warps (4m x 2n), warp tile 32x64, KTILE=64 (4 k16 steps),
// 2-stage cp.async, ldmatrix.x4 fragments. Smem row stride 36 words (32 data + 4 pad).
// mode bits: 1=relu, 16=+residual fp16(R), 8=store fp16 Ch
#define SMS 36
#define KDIM 512
#define KT 64
#define NKT (KDIM / KT)            // 8
#define SA_WORDS (128 * SMS)       // 4608
#define STG_WORDS (2 * SA_WORDS)   // 9216 (A + B)
#define STG_BYTES (STG_WORDS * 4)  // 36864
#define GEMM_SMEM_BYTES (2 * STG_BYTES)  // 73728

__global__ __launch_bounds__(256, 2)
void gemm_h(const __half* __restrict__ A0, const __half* __restrict__ A1,
            const __half* __restrict__ A2,
            const __half* __restrict__ W, const float* __restrict__ bias,
            const __half* __restrict__ R0, const __half* __restrict__ R1,
            const __half* __restrict__ R2,
            __half* __restrict__ Ch0, __half* __restrict__ Ch1, __half* __restrict__ Ch2,
            int N, int mode)
{
    extern __shared__ __align__(16) uint32_t smem[];
    const int tid = threadIdx.x, wid = tid >> 5, lane = tid & 31;
    const int g = lane >> 2, tg = lane & 3;
    const int z = blockIdx.z;
    const __half* A = (z == 0) ? A0 : (z == 1) ? A1 : A2;
    const __half* R = (z == 0) ? R0 : (z == 1) ? R1 : R2;
    __half*      Ch = (z == 0) ? Ch0 : (z == 1) ? Ch1 : Ch2;
    const int m0 = blockIdx.y * 128;
    const int n0 = blockIdx.x * 128;
    const int moff = (wid & 3) * 32;
    const int noff = (wid >> 2) * 64;
    const __half* Ag = A + (size_t)m0 * KDIM;
    const __half* Bg = W + (size_t)n0 * KDIM;

    const uint32_t sbase = smem_u32(smem);

    // ldmatrix per-lane addressing: row-in-group + k-half select within a k16 chunk
    const int lrow8 = ((lane >> 3) & 1) * 8 + (lane & 7);
    const int lk4   = (lane >> 4) * 4;
    uint32_t aoff[2], boff[4];
    #pragma unroll
    for (int mt = 0; mt < 2; mt++)
        aoff[mt] = ((moff + mt * 16 + lrow8) * SMS + lk4) * 4;
    #pragma unroll
    for (int ntp = 0; ntp < 4; ntp++)
        boff[ntp] = ((noff + ntp * 16 + lrow8) * SMS + lk4) * 4;

    float acc[2][8][4];
    #pragma unroll
    for (int mt = 0; mt < 2; mt++)
        #pragma unroll
        for (int nt = 0; nt < 8; nt++)
            #pragma unroll
            for (int q = 0; q < 4; q++) acc[mt][nt][q] = 0.f;

    // fill: A 1024 16B-chunks (4/thread), B 1024 (4/thread).
    // chunk c: row = c>>3 (0..127), sub = c&7; word off = row*SMS + sub*4;
    // global halfs = row*KDIM + k0 + sub*8
    #define FILL_STAGE(stg, k0)                                                      \
    do {                                                                             \
        const uint32_t wA = sbase + (stg) * STG_BYTES;                               \
        const uint32_t wB = wA + SA_WORDS * 4;                                       \
        _Pragma("unroll")                                                            \
        for (int p = 0; p < 4; p++) {                                                \
            const int c = tid + 256 * p;                                             \
            const int row = c >> 3;                                                  \
            const int sub = c & 7;                                                   \
            CP_ASYNC16(wA + (row * SMS + sub * 4) * 4,                               \
                       &Ag[(size_t)row * KDIM + (k0) + sub * 8]);                    \
            CP_ASYNC16(wB + (row * SMS + sub * 4) * 4,                               \
                       &Bg[(size_t)row * KDIM + (k0) + sub * 8]);                    \
        }                                                                            \
    } while (0)

    FILL_STAGE(0, 0);
    CP_COMMIT();

    for (int t = 0; t < NKT; t++) {
        if (t + 1 < NKT) { FILL_STAGE((t + 1) & 1, (t + 1) * KT); }
        CP_COMMIT();
        CP_WAIT1();               // fill(t) resident; fill(t+1) may be in flight
        __syncthreads();

        const uint32_t Ab = sbase + (t & 1) * STG_BYTES;
        const uint32_t Bb = Ab + SA_WORDS * 4;

        #pragma unroll
        for (int ks = 0; ks < 4; ks++) {
            const uint32_t kb4 = ks * 32;     // k16 chunk: 8 words = 32 bytes
            uint32_t af[2][4], bf[8][2];
            #pragma unroll
            for (int mt = 0; mt < 2; mt++)
                LDSM4(af[mt][0], af[mt][1], af[mt][2], af[mt][3], Ab + aoff[mt] + kb4);
            #pragma unroll
            for (int ntp = 0; ntp < 4; ntp++)
                LDSM4(bf[2*ntp][0], bf[2*ntp+1][0], bf[2*ntp][1], bf[2*ntp+1][1],
                      Bb + boff[ntp] + kb4);
            #pragma unroll
            for (int mt = 0; mt < 2; mt++)
                #pragma unroll
                for (int nt = 0; nt < 8; nt++) {
                    asm volatile(
                        "mma.sync.aligned.m16n8k16.row.col.f32.f16.f16.f32 "
                        "{%0,%1,%2,%3}, {%4,%5,%6,%7}, {%8,%9}, {%0,%1,%2,%3};"
                        : "+f"(acc[mt][nt][0]), "+f"(acc[mt][nt][1]),
                          "+f"(acc[mt][nt][2]), "+f"(acc[mt][nt][3])
                        : "r"(af[mt][0]), "r"(af[mt][1]), "r"(af[mt][2]), "r"(af[mt][3]),
                          "r"(bf[nt][0]), "r"(bf[nt][1]));
                }
        }
        __syncthreads();
    }

    // ---- epilogue ----
    #pragma unroll
    for (int mt = 0; mt < 2; mt++) {
        #pragma unroll
        for (int nt = 0; nt < 8; nt++) {
            const int n = n0 + noff + nt * 8 + 2 * tg;
            const int ra = m0 + moff + mt * 16 + g;
            const int rb = ra + 8;
            float bx = bias[n], by = bias[n + 1];
            float2 v0 = make_float2(acc[mt][nt][0] + bx, acc[mt][nt][1] + by);
            float2 v1 = make_float2(acc[mt][nt][2] + bx, acc[mt][nt][3] + by);
            if (mode & 1) {
                v0.x = fmaxf(v0.x, 0.f); v0.y = fmaxf(v0.y, 0.f);
                v1.x = fmaxf(v1.x, 0.f); v1.y = fmaxf(v1.y, 0.f);
            }
            if (mode & 16) {
                float2 r0v = __half22float2(*(const __half2*)&R[(size_t)ra * N + n]);
                float2 r1v = __half22float2(*(const __half2*)&R[(size_t)rb * N + n]);
                v0.x += r0v.x; v0.y += r0v.y;
                v1.x += r1v.x; v1.y += r1v.y;
            }
            if (mode & 8) {
                __half2 h0 = __floats2half2_rn(v0.x, v0.y);
                __half2 h1 = __floats2half2_rn(v1.x, v1.y);
                *(__half2*)&Ch[(size_t)ra * N + n] = h0;
                *(__half2*)&Ch[(size_t)rb * N + n] = h1;
            }
        }
    }
}

// ================== warp-per-row fused gemv + polar + rotation-scan + score ==========
#define FULLM 0xffffffffu

__device__ __forceinline__ void rot_pass(float* xl, const float* sl, const float* cl,
                                         int lane)
{
    float x0 = __shfl_sync(FULLM, xl[0], 0);
    float x1 = __shfl_sync(FULLM, xl[1], 0);
    float s0 = __shfl_sync(FULLM, sl[0], 0);
    float c0 = __shfl_sync(FULLM, cl[0], 0);
    float x0pre = c0 * x0 - s0 * x1;

    float nx[8];
    #pragma unroll
    for (int k = 0; k < 7; k++) nx[k] = xl[k + 1];
    nx[7] = __shfl_down_sync(FULLM, xl[0], 1);
    if (lane == 31) nx[7] = x0pre;

    float A = 1.f, B = 0.f;
    #pragma unroll
    for (int k = 0; k < 8; k++) {
        B = fmaf(sl[k], B, cl[k] * nx[k]);
        A *= sl[k];
    }
    #pragma unroll
    for (int d = 1; d < 32; d <<= 1) {
        float pA = __shfl_up_sync(FULLM, A, d);
        float pB = __shfl_up_sync(FULLM, B, d);
        if (lane >= d) {
            B = fmaf(A, pB, B);
            A *= pA;
        }
    }
    float eA = __shfl_up_sync(FULLM, A, 1);
    float eB = __shfl_up_sync(FULLM, B, 1);
    if (lane == 0) { eA = 1.f; eB = 0.f; }
    float cur = fmaf(eA, x0, eB);

    float w[8];
    #pragma unroll
    for (int k = 0; k < 8; k++) {
        w[k] = cl[k] * cur - sl[k] * nx[k];
        cur = fmaf(sl[k], cur, cl[k] * nx[k]);
    }
    float x0fin = __shfl_sync(FULLM, cur, 31);
    #pragma unroll
    for (int k = 0; k < 8; k++) xl[k] = w[k];
    if (lane == 0) xl[0] = x0fin;
}

__device__ __forceinline__ void load8h(const __half* p, float* v) {
    uint4 a = *(const uint4*)p;
    const __half2* hp = (const __half2*)&a;
    float2 f0 = __half22float2(hp[0]);
    float2 f1 = __half22float2(hp[1]);
    float2 f2 = __half22float2(hp[2]);
    float2 f3 = __half22float2(hp[3]);
    v[0]=f0.x; v[1]=f0.y; v[2]=f1.x; v[3]=f1.y;
    v[4]=f2.x; v[5]=f2.y; v[6]=f3.x; v[7]=f3.y;
}

__global__ __launch_bounds__(256)
void polar_score(const __half* __restrict__ Vh, const __half* __restrict__ Vt,
                 const __half* __restrict__ TH,
                 const __half* __restrict__ Eh, const __half* __restrict__ Er,
                 const __half* __restrict__ Et,
                 const float* __restrict__ Wre, const float* __restrict__ bre,
                 const float* __restrict__ Wrr, const float* __restrict__ brr,
                 const float* __restrict__ sim,
                 const float* __restrict__ ga_rho, const float* __restrict__ gb_rho,
                 const float* __restrict__ ga_phi, const float* __restrict__ gb_phi,
                 float* __restrict__ out)
{
    const int b = (blockIdx.x * blockDim.x + threadIdx.x) >> 5;
    const int lane = threadIdx.x & 31;
    if (b >= NB) return;

    // ---- fused gemv: s1 = Eh.Wre, s2 = Er.Wrr, s3 = Et.Wre (16 elems/lane) ----
    float s1 = 0.f, s2 = 0.f, s3 = 0.f;
    {
        const int k0 = lane * 16;
        float e[8], wv[8];
        #pragma unroll
        for (int hseg = 0; hseg < 2; hseg++) {
            const int k = k0 + hseg * 8;
            #pragma unroll
            for (int j = 0; j < 8; j += 4)
                *(float4*)&wv[j] = *(const float4*)&Wre[k + j];
            load8h(Eh + (size_t)b * HD + k, e);
            #pragma unroll
            for (int j = 0; j < 8; j++) s1 = fmaf(e[j], wv[j], s1);
            load8h(Et + (size_t)b * HD + k, e);
            #pragma unroll
            for (int j = 0; j < 8; j++) s3 = fmaf(e[j], wv[j], s3);
            #pragma unroll
            for (int j = 0; j < 8; j += 4)
                *(float4*)&wv[j] = *(const float4*)&Wrr[k + j];
            load8h(Er + (size_t)b * HD + k, e);
            #pragma unroll
            for (int j = 0; j < 8; j++) s2 = fmaf(e[j], wv[j], s2);
        }
    }

    // ---- load u_h, u_t + norms ----
    float uh[8], ut[8];
    load8h(Vh + (size_t)b * DV + lane * 8, uh);
    load8h(Vt + (size_t)b * DV + lane * 8, ut);

    float nh = 0.f, nt2 = 0.f;
    #pragma unroll
    for (int k = 0; k < 8; k++) { nh = fmaf(uh[k], uh[k], nh); nt2 = fmaf(ut[k], ut[k], nt2); }
    #pragma unroll
    for (int o = 16; o > 0; o >>= 1) {
        nh  += __shfl_xor_sync(FULLM, nh,  o);
        nt2 += __shfl_xor_sync(FULLM, nt2, o);
    }
    float ih = 1.f / (sqrtf(nh) + EPSF);
    float it = 1.f / (sqrtf(nt2) + EPSF);
    #pragma unroll
    for (int k = 0; k < 8; k++) { uh[k] *= ih; ut[k] *= it; }

    // ---- rotations ----
    float sl[8], cl[8], tv[8];
    load8h(TH + (size_t)b * NP + lane * 8, tv);
    #pragma unroll
    for (int k = 0; k < 8; k++)
        sincospi_t(fast_tanh(tv[k]), sl[k], cl[k]);

    float w[8];
    #pragma unroll
    for (int k = 0; k < 8; k++) w[k] = uh[k];
    rot_pass(w, sl, cl, lane);

    load8h(TH + (size_t)b * NP + 256 + lane * 8, tv);
    #pragma unroll
    for (int k = 0; k < 8; k++)
        sincospi_t(fast_tanh(tv[k]), sl[k], cl[k]);
    rot_pass(w, sl, cl, lane);

    // ---- dots + combined reduction (incl. gemv partials) ----
    float ssq = 0.f, dhr = 0.f, drt = 0.f, dht = 0.f;
    #pragma unroll
    for (int k = 0; k < 8; k++) {
        ssq = fmaf(w[k], w[k], ssq);
        dhr = fmaf(w[k], uh[k], dhr);
        drt = fmaf(w[k], ut[k], drt);
        dht = fmaf(uh[k], ut[k], dht);
    }
    #pragma unroll
    for (int o = 16; o > 0; o >>= 1) {
        ssq += __shfl_xor_sync(FULLM, ssq, o);
        dhr += __shfl_xor_sync(FULLM, dhr, o);
        drt += __shfl_xor_sync(FULLM, drt, o);
        dht += __shfl_xor_sync(FULLM, dht, o);
        s1  += __shfl_xor_sync(FULLM, s1,  o);
        s2  += __shfl_xor_sync(FULLM, s2,  o);
        s3  += __shfl_xor_sync(FULLM, s3,  o);
    }

    if (lane != 0) return;

    float nr = sqrtf(ssq);
    float inv_rot = 1.f / (nr + EPSF);
    float dhr_n = dhr * inv_rot;
    float dotc = fminf(fmaxf(dhr_n, -1.f + EPSF), 1.f - EPSF);
    float omega = acosf(dotc);
    float sin_om = sinf(omega);
    float sv = sim[b];
    float grho = 1.f / (1.f + expf(-(ga_rho[0] * sv + gb_rho[0])));
    float gphi = 1.f / (1.f + expf(-(ga_phi[0] * sv + gb_phi[0])));
    float ca, cb;
    if (omega > DELTAF) {
        float iso = 1.f / (sin_om + EPSF);
        ca = sinf((1.f - gphi) * omega) * iso;
        cb = sinf(gphi * omega) * iso;
    } else {
        ca = 1.f - gphi; cb = gphi;
    }
    float nrn = nr * inv_rot;
    float np2 = ca * ca + cb * cb * nrn * nrn + 2.f * ca * cb * dhr_n;
    float npv = sqrtf(fmaxf(np2, 0.f));
    float inv_np = 1.f / (npv + EPSF);
    float dpt = (ca * dht + cb * drt * inv_rot) * inv_np;

    float reh_v = s1 + bre[0];
    float rrr_v = s2 + brr[0];
    float ret_v = s3 + bre[0];
    float rho_h = fminf(softplusf(reh_v), RHO_MAXF);
    float rho_p = fminf(fmaxf(rho_h + rrr_v * grho, 0.f), RHO_MAXF);
    float rho_t = fminf(softplusf(ret_v), RHO_MAXF);
    out[b] = -coshf(rho_p) * coshf(rho_t) + sinhf(rho_p) * sinhf(rho_t) * dpt;
}

// ---------------- launch --------------------------------------------------------------
extern "C" void kernel_launch(void* const* d_in, const int* in_sizes, int n_in,
                              void* d_out, int out_size)
{
    const float* ent  = (const float*)d_in[0];
    const float* rel  = (const float*)d_in[1];
    const float* lab  = (const float*)d_in[2];
    const float* sim  = (const float*)d_in[3];
    const float* Wv   = (const float*)d_in[4];
    const float* bv   = (const float*)d_in[5];
    const float* Wre  = (const float*)d_in[6];
    const float* bre  = (const float*)d_in[7];
    const float* Wrr  = (const float*)d_in[8];
    const float* brr  = (const float*)d_in[9];
    const float* Wt   = (const float*)d_in[10];
    const float* bt   = (const float*)d_in[11];
    const float* ga_rho = (const float*)d_in[12];
    const float* gb_rho = (const float*)d_in[13];
    const float* ga_phi = (const float*)d_in[14];
    const float* gb_phi = (const float*)d_in[15];
    const float* W1   = (const float*)d_in[16];
    const float* b1   = (const float*)d_in[17];
    const float* W2   = (const float*)d_in[18];
    const float* b2   = (const float*)d_in[19];
    float* out = (float*)d_out;

    __half *hEnt, *hRel, *hLab, *hH0, *hH1, *hH2, *hEh, *hEr, *hEt;
    __half *hW1, *hW2, *hWv, *hWt;
    cudaGetSymbolAddress((void**)&hEnt, g_hEnt);
    cudaGetSymbolAddress((void**)&hRel, g_hRel);
    cudaGetSymbolAddress((void**)&hLab, g_hLab);
    cudaGetSymbolAddress((void**)&hH0,  g_hH0);
    cudaGetSymbolAddress((void**)&hH1,  g_hH1);
    cudaGetSymbolAddress((void**)&hH2,  g_hH2);
    cudaGetSymbolAddress((void**)&hEh,  g_hEh);
    cudaGetSymbolAddress((void**)&hEr,  g_hEr);
    cudaGetSymbolAddress((void**)&hEt,  g_hEt);
    cudaGetSymbolAddress((void**)&hW1,  g_hW1);
    cudaGetSymbolAddress((void**)&hW2,  g_hW2);
    cudaGetSymbolAddress((void**)&hWv,  g_hWv);
    cudaGetSymbolAddress((void**)&hWt,  g_hWt);

    cudaFuncSetAttribute(gemm_h, cudaFuncAttributeMaxDynamicSharedMemorySize,
                         GEMM_SMEM_BYTES);

    const int BIG = NB * HD;
    cvt3_f2h<<<dim3(BIG / (256 * 8), 3), 256>>>(ent, rel, lab, hEnt, hRel, hLab);
    cvtW_f2h<<<dim3((HD * HD) / (256 * 8), 4), 256>>>(W1, W2, Wv, Wt,
                                                      hW1, hW2, hWv, hWt);

    const dim3 blk(256);
    // layer 1: hH_z = fp16(relu(X_z @ W1^T + b1))             mode 1|8 = 9
    gemm_h<<<dim3(HD/128, NB/128, 3), blk, GEMM_SMEM_BYTES>>>(
        hEnt, hRel, hLab, hW1, b1, nullptr, nullptr, nullptr,
        hH0, hH1, hH2, HD, 9);
    // layer 2: hE_z = fp16(H_z @ W2^T + b2 + X_z[fp16])       mode 16|8 = 24
    gemm_h<<<dim3(HD/128, NB/128, 3), blk, GEMM_SMEM_BYTES>>>(
        hH0, hH1, hH2, hW2, b2, hEnt, hRel, hLab,
        hEh, hEr, hEt, HD, 24);
    // Wv projections -> fp16 (reuse hH0/hH1)                  mode 8
    gemm_h<<<dim3(DV/128, NB/128, 2), blk, GEMM_SMEM_BYTES>>>(
        hEh, hEt, nullptr, hWv, bv, nullptr, nullptr, nullptr,
        hH0, hH1, nullptr, DV, 8);
    // theta logits -> fp16 (reuse hH2)                        mode 8
    gemm_h<<<dim3(NP/128, NB/128, 1), blk, GEMM_SMEM_BYTES>>>(
        hEr, nullptr, nullptr, hWt, bt, nullptr, nullptr, nullptr,
        hH2, nullptr, nullptr, NP, 8);

    // fused warp-per-row: gemv (rho logits) + normalize + Givens scan + score
    polar_score<<<(NB * 32) / 256, 256>>>(hH0, hH1, hH2, hEh, hEr, hEt,
                                          Wre, bre, Wrr, brr, sim,
                                          ga_rho, gb_rho, ga_phi, gb_phi, out);
    (void)in_sizes; (void)n_in; (void)out_size;
}